// round 14
// baseline (speedup 1.0000x reference)
#include <cuda_runtime.h>
#include <cstdint>

// ---------------------------------------------------------------------------
// Problem constants
// ---------------------------------------------------------------------------
#define NF   768
#define NB1  512
#define NN1  50
#define NB2  16
#define NN2  32
#define M1   (NB1*NN1)    // 25600
#define NC   400
#define NF2  (2*NF)
#define NZW  1536         // combined z|xw width

// column permutation within 16-groups (for LDS.64 B-fragment pairs)
#define COLPERM(n) (((n) & ~15) | (((n) & 7) << 1) | (((n) >> 3) & 1))

// ---------------------------------------------------------------------------
// Scratch (device globals)
// ---------------------------------------------------------------------------
__device__ float g_zxw [(size_t)M1 * NZW];    // z | xw, ld=1536
__device__ float g_xw  [(size_t)M1 * NF];
__device__ float g_x   [(size_t)M1 * NF];
__device__ float g_adj [(size_t)NB1 * NN1 * NN1];
__device__ float g_mean[(size_t)NB1 * NF];
__device__ float g_mean2[(size_t)NB2 * NF];
__device__ float g_hc  [(size_t)NB2 * NF];
__device__ float g_wcomb[(size_t)NF * NZW];   // [K=768][N=1536]: A | W0, col-permuted
__device__ float g_w1p [(size_t)NF * NF];     // W1, col-permuted (raw bits)
__device__ float g_wqT [(size_t)NF * NF];
__device__ float g_cvec[2 * NF + 1];          // c1 | c2 | c3
__device__ float g_cpart[32 * 2 * NF];

// ---------------------------------------------------------------------------
// helpers
// ---------------------------------------------------------------------------
__device__ __forceinline__ uint32_t smem_to_u32(const void* p) {
    uint32_t a;
    asm("{ .reg .u64 t; cvta.to.shared.u64 t, %1; cvt.u32.u64 %0, t; }"
        : "=r"(a) : "l"(p));
    return a;
}

__device__ __forceinline__ uint32_t f2tf32(float f) {
    uint32_t r;
    asm("cvt.rna.tf32.f32 %0, %1;" : "=r"(r) : "f"(f));
    return r;
}

__device__ __forceinline__ void mma_tf32(float* d, const uint32_t* a, const uint32_t* b) {
    asm volatile(
        "mma.sync.aligned.m16n8k8.row.col.f32.tf32.tf32.f32 "
        "{%0,%1,%2,%3}, {%4,%5,%6,%7}, {%8,%9}, {%0,%1,%2,%3};"
        : "+f"(d[0]), "+f"(d[1]), "+f"(d[2]), "+f"(d[3])
        : "r"(a[0]), "r"(a[1]), "r"(a[2]), "r"(a[3]), "r"(b[0]), "r"(b[1]));
}

__device__ __forceinline__ void cp_async16(uint32_t dst, const void* src) {
    asm volatile("cp.async.cg.shared.global [%0], [%1], 16;"
                 :: "r"(dst), "l"(src) : "memory");
}
#define CP_COMMIT() asm volatile("cp.async.commit_group;" ::: "memory")
#define CP_WAIT0()  asm volatile("cp.async.wait_group 0;" ::: "memory")

__device__ __forceinline__ unsigned long long fma_f32x2(
    unsigned long long a, unsigned long long b, unsigned long long c) {
    unsigned long long d;
    asm("fma.rn.f32x2 %0, %1, %2, %3;" : "=l"(d) : "l"(a), "l"(b), "l"(c));
    return d;
}
__device__ __forceinline__ unsigned long long pack_f32x2(float lo, float hi) {
    unsigned long long p;
    asm("mov.b64 %0, {%1, %2};" : "=l"(p) : "f"(lo), "f"(hi));
    return p;
}
__device__ __forceinline__ void unpack_f32x2(unsigned long long p, float& lo, float& hi) {
    asm("mov.b64 {%0, %1}, %2;" : "=f"(lo), "=f"(hi) : "l"(p));
}

// ---------------------------------------------------------------------------
// Pipelined TF32 GEMM: C = A[M,K] @ B[K,N]; HMMA truncates both operands.
// B is COLPERM column-permuted in global. 128x128x32 tile, 256 threads.
// A: float4 reg-prefetch, raw-bit STS with row-local j-XOR swizzle.
// B: cp.async double-buffered; BNP=136 + COLPERM -> conflict-free LDS.64 frags.
// M%128==0, N%128==0, K%32==0.
// ---------------------------------------------------------------------------
#define GEMM_SMEM 75776

__global__ __launch_bounds__(256, 2)
void gemm_tf32(const float* __restrict__ A, const float* __restrict__ B,
               float* __restrict__ C, int M, int N, int K,
               int lda, int ldb, int ldc)
{
    constexpr int BK = 32, AKP = 40, BNP = 136;
    constexpr int ASZ = 128 * AKP, BSZ = BK * BNP;
    extern __shared__ uint32_t smg[];
    uint32_t* Ab = smg;             // [2][ASZ]
    uint32_t* Bb = smg + 2 * ASZ;   // [2][BSZ]
    const uint32_t sbB = smem_to_u32(Bb);

    const int tid  = threadIdx.x;
    const int wid  = tid >> 5, lane = tid & 31;
    const int gid  = lane >> 2, cq = lane & 3;
    const int wm   = (wid >> 2) * 64, wn = (wid & 3) * 32;
    const int row0 = blockIdx.y * 128, col0 = blockIdx.x * 128;
    const int NK   = K / BK;
    const int cqx  = 2 * (cq ^ (gid & 3));

    int bk[4], bn4[4];
    #pragma unroll
    for (int i = 0; i < 4; i++) {
        int u = tid + i * 256;
        bk[i]  = u >> 5;
        bn4[i] = (u & 31) * 4;
    }

    #pragma unroll
    for (int i = 0; i < 4; i++)
        cp_async16(sbB + (uint32_t)(bk[i] * BNP + bn4[i]) * 4,
                   B + (size_t)bk[i] * ldb + col0 + bn4[i]);
    CP_COMMIT();

    float4 rA[4];
    #pragma unroll
    for (int i = 0; i < 4; i++) {
        int u = tid + i * 256, m = u >> 3, kq = u & 7;
        rA[i] = *reinterpret_cast<const float4*>(A + (size_t)(row0 + m) * lda + 4 * kq);
    }

    float acc[4][4][4];
    #pragma unroll
    for (int i = 0; i < 4; i++)
        #pragma unroll
        for (int j = 0; j < 4; j++)
            #pragma unroll
            for (int q = 0; q < 4; q++) acc[i][j][q] = 0.f;

    for (int s = 0; s < NK; s++) {
        const int p = s & 1;
        uint32_t* Ap = Ab + p * ASZ;
        uint32_t* Bp = Bb + p * BSZ;

        #pragma unroll
        for (int i = 0; i < 4; i++) {
            int u = tid + i * 256, m = u >> 3, kq = u & 7;
            int r = m & 3;
            int base = m * AKP + 8 * (kq >> 1) + (kq & 1);
            Ap[base + 2 * (0 ^ r)] = __float_as_uint(rA[i].x);
            Ap[base + 2 * (1 ^ r)] = __float_as_uint(rA[i].y);
            Ap[base + 2 * (2 ^ r)] = __float_as_uint(rA[i].z);
            Ap[base + 2 * (3 ^ r)] = __float_as_uint(rA[i].w);
        }
        CP_WAIT0();
        __syncthreads();
        if (s + 1 < NK) {
            const float* Bn = B + (size_t)(s + 1) * BK * ldb + col0;
            #pragma unroll
            for (int i = 0; i < 4; i++)
                cp_async16(sbB + (uint32_t)((p ^ 1) * BSZ + bk[i] * BNP + bn4[i]) * 4,
                           Bn + (size_t)bk[i] * ldb + bn4[i]);
            CP_COMMIT();
            #pragma unroll
            for (int i = 0; i < 4; i++) {
                int u = tid + i * 256, m = u >> 3, kq = u & 7;
                rA[i] = *reinterpret_cast<const float4*>(
                    A + (size_t)(row0 + m) * lda + (s + 1) * BK + 4 * kq);
            }
        }

        #pragma unroll
        for (int st = 0; st < 4; st++) {
            uint32_t af[4][4];
            #pragma unroll
            for (int mt = 0; mt < 4; mt++) {
                int r0 = wm + mt * 16 + gid;
                uint2 t0 = *reinterpret_cast<const uint2*>(&Ap[(r0    ) * AKP + 8 * st + cqx]);
                uint2 t1 = *reinterpret_cast<const uint2*>(&Ap[(r0 + 8) * AKP + 8 * st + cqx]);
                af[mt][0] = t0.x; af[mt][1] = t1.x; af[mt][2] = t0.y; af[mt][3] = t1.y;
            }
            // B frags: col-permuted storage -> (n, n+8) adjacent -> LDS.64;
            // BNP=136 makes these conflict-free (banks 8cq+2gid bijective).
            uint32_t bf[4][2];
            {
                const uint32_t* r0p = &Bp[(8 * st + cq    ) * BNP + wn + 2 * gid];
                const uint32_t* r1p = &Bp[(8 * st + cq + 4) * BNP + wn + 2 * gid];
                uint2 b0 = *reinterpret_cast<const uint2*>(r0p);
                uint2 b1 = *reinterpret_cast<const uint2*>(r1p);
                uint2 b2 = *reinterpret_cast<const uint2*>(r0p + 16);
                uint2 b3 = *reinterpret_cast<const uint2*>(r1p + 16);
                bf[0][0] = b0.x; bf[1][0] = b0.y; bf[0][1] = b1.x; bf[1][1] = b1.y;
                bf[2][0] = b2.x; bf[3][0] = b2.y; bf[2][1] = b3.x; bf[3][1] = b3.y;
            }
            #pragma unroll
            for (int mt = 0; mt < 4; mt++)
                #pragma unroll
                for (int nt = 0; nt < 4; nt++)
                    mma_tf32(acc[mt][nt], af[mt], bf[nt]);
        }
    }

    #pragma unroll
    for (int mt = 0; mt < 4; mt++) {
        int rlo = row0 + wm + mt * 16 + gid;
        int rhi = rlo + 8;
        #pragma unroll
        for (int nt = 0; nt < 4; nt++) {
            int cc = col0 + wn + nt * 8 + 2 * cq;
            C[(size_t)rlo * ldc + cc    ] = acc[mt][nt][0];
            C[(size_t)rlo * ldc + cc + 1] = acc[mt][nt][1];
            C[(size_t)rhi * ldc + cc    ] = acc[mt][nt][2];
            C[(size_t)rhi * ldc + cc + 1] = acc[mt][nt][3];
        }
    }
}

// ---------------------------------------------------------------------------
// Split-tf32 GEMM (fp32-accurate) — prep only (A = wq^T @ wk).
// Output tf32-rounded and COLPERM-permuted (feeds gemm_tf32 as B).
// ---------------------------------------------------------------------------
__global__ __launch_bounds__(256, 1)
void gemm_split(const float* __restrict__ A, const float* __restrict__ B,
                float* __restrict__ C, int M, int N, int K,
                int lda, int ldb, int ldc)
{
    constexpr int BK = 32, AKP = 40, BNP = 136;
    constexpr int ASZ = 128 * AKP, BSZ = BK * BNP;
    extern __shared__ uint32_t smg[];
    uint32_t* Ah = smg;
    uint32_t* Al = smg + ASZ;
    uint32_t* Bh = smg + 2 * ASZ;
    uint32_t* Bl = smg + 2 * ASZ + BSZ;

    const int tid  = threadIdx.x;
    const int wid  = tid >> 5, lane = tid & 31;
    const int gid  = lane >> 2, cq = lane & 3;
    const int wm   = (wid >> 2) * 64, wn = (wid & 3) * 32;
    const int row0 = blockIdx.y * 128, col0 = blockIdx.x * 128;

    float acc[4][4][4];
    #pragma unroll
    for (int i = 0; i < 4; i++)
        #pragma unroll
        for (int j = 0; j < 4; j++)
            #pragma unroll
            for (int q = 0; q < 4; q++) acc[i][j][q] = 0.f;

    for (int k0 = 0; k0 < K; k0 += BK) {
        __syncthreads();
        #pragma unroll
        for (int i = 0; i < 4; i++) {
            int u = tid + i * 256, m = u >> 3, kq = u & 7;
            int gm = row0 + m;
            float4 v = (gm < M) ? *reinterpret_cast<const float4*>(A + (size_t)gm * lda + k0 + 4 * kq)
                                : make_float4(0.f, 0.f, 0.f, 0.f);
            int base = m * AKP + 8 * (kq >> 1) + (kq & 1);
            float xs[4] = {v.x, v.y, v.z, v.w};
            #pragma unroll
            for (int j = 0; j < 4; j++) {
                uint32_t hi = f2tf32(xs[j]);
                Ah[base + 2 * j] = hi;
                Al[base + 2 * j] = f2tf32(xs[j] - __uint_as_float(hi));
            }
        }
        #pragma unroll
        for (int i = 0; i < 4; i++) {
            int u = tid + i * 256, k = u >> 5, nq = u & 31;
            int gn = col0 + 4 * nq;
            const float* bp = B + (size_t)(k0 + k) * ldb + gn;
            int base = k * BNP + 4 * nq;
            #pragma unroll
            for (int j = 0; j < 4; j++) {
                float x = (gn + j < N) ? bp[j] : 0.f;
                uint32_t hi = f2tf32(x);
                Bh[base + j] = hi;
                Bl[base + j] = f2tf32(x - __uint_as_float(hi));
            }
        }
        __syncthreads();

        #pragma unroll
        for (int s = 0; s < 4; s++) {
            uint32_t ah[4][4], al[4][4];
            #pragma unroll
            for (int mt = 0; mt < 4; mt++) {
                int r0 = wm + mt * 16 + gid;
                uint2 t0 = *reinterpret_cast<const uint2*>(&Ah[(r0    ) * AKP + 8 * s + 2 * cq]);
                uint2 t1 = *reinterpret_cast<const uint2*>(&Ah[(r0 + 8) * AKP + 8 * s + 2 * cq]);
                ah[mt][0] = t0.x; ah[mt][1] = t1.x; ah[mt][2] = t0.y; ah[mt][3] = t1.y;
                uint2 u0 = *reinterpret_cast<const uint2*>(&Al[(r0    ) * AKP + 8 * s + 2 * cq]);
                uint2 u1 = *reinterpret_cast<const uint2*>(&Al[(r0 + 8) * AKP + 8 * s + 2 * cq]);
                al[mt][0] = u0.x; al[mt][1] = u1.x; al[mt][2] = u0.y; al[mt][3] = u1.y;
            }
            uint32_t bh[4][2], bl[4][2];
            #pragma unroll
            for (int nt = 0; nt < 4; nt++) {
                int cn = wn + nt * 8 + gid;
                bh[nt][0] = Bh[(8 * s + cq    ) * BNP + cn];
                bh[nt][1] = Bh[(8 * s + cq + 4) * BNP + cn];
                bl[nt][0] = Bl[(8 * s + cq    ) * BNP + cn];
                bl[nt][1] = Bl[(8 * s + cq + 4) * BNP + cn];
            }
            #pragma unroll
            for (int mt = 0; mt < 4; mt++)
                #pragma unroll
                for (int nt = 0; nt < 4; nt++) {
                    mma_tf32(acc[mt][nt], ah[mt], bh[nt]);
                    mma_tf32(acc[mt][nt], ah[mt], bl[nt]);
                    mma_tf32(acc[mt][nt], al[mt], bh[nt]);
                }
        }
    }

    #pragma unroll
    for (int mt = 0; mt < 4; mt++) {
        int rlo = row0 + wm + mt * 16 + gid;
        int rhi = rlo + 8;
        #pragma unroll
        for (int nt = 0; nt < 4; nt++) {
            int cc = col0 + wn + nt * 8 + 2 * cq;
            if (rlo < M) {
                if (cc     < N) C[(size_t)rlo * ldc + COLPERM(cc    )] = __uint_as_float(f2tf32(acc[mt][nt][0]));
                if (cc + 1 < N) C[(size_t)rlo * ldc + COLPERM(cc + 1)] = __uint_as_float(f2tf32(acc[mt][nt][1]));
            }
            if (rhi < M) {
                if (cc     < N) C[(size_t)rhi * ldc + COLPERM(cc    )] = __uint_as_float(f2tf32(acc[mt][nt][2]));
                if (cc + 1 < N) C[(size_t)rhi * ldc + COLPERM(cc + 1)] = __uint_as_float(f2tf32(acc[mt][nt][3]));
            }
        }
    }
}

// ---------------------------------------------------------------------------
// adj_mma: per batch b, split-tf32 dot = z @ x^T; r1/r2 computed in-kernel.
// adj = dot^2 / max(rowsum(dot^2), 1e-12)
// ---------------------------------------------------------------------------
template<int NN>
__global__ __launch_bounds__(256, 2)
void adj_mma(const float* __restrict__ Z, int ldz,
             const float* __restrict__ X, int ldx,
             const float* __restrict__ cv, float* __restrict__ ADJ)
{
    __shared__ __align__(16) uint32_t sbuf[9728];
    __shared__ float r1s[64], r2s[64];
    uint32_t* qh = sbuf;
    uint32_t* ql = sbuf + 2560;
    uint32_t* kh = sbuf + 5120;
    uint32_t* kl = sbuf + 7424;

    const int b = blockIdx.x, tid = threadIdx.x;
    const int wid = tid >> 5, lane = tid & 31;
    const int gid = lane >> 2, cq = lane & 3;
    const int wm = (wid >> 2) * 32, wn = (wid & 3) * 16;

    const float c3 = cv[2 * NF];
    const int rn = tid >> 2;
    const int rq = tid & 3;

    const float* q = Z + (size_t)b * NN * ldz;
    const float* k = X + (size_t)b * NN * ldx;

    float acc[2][2][4];
    #pragma unroll
    for (int a = 0; a < 2; a++)
        #pragma unroll
        for (int c = 0; c < 2; c++)
            #pragma unroll
            for (int e = 0; e < 4; e++) acc[a][c][e] = 0.f;

    float racc1 = 0.f, racc2 = 0.f;

    for (int k0 = 0; k0 < NF; k0 += 32) {
        __syncthreads();
        #pragma unroll
        for (int i = 0; i < 2; i++) {
            int u = tid + i * 256;
            int m = u >> 3, kq = u & 7;
            float4 v = make_float4(0.f, 0.f, 0.f, 0.f);
            if (m < NN) v = *reinterpret_cast<const float4*>(q + (size_t)m * ldz + k0 + 4 * kq);
            int base = m * 40 + 8 * (kq >> 1) + (kq & 1);
            float xs[4] = {v.x, v.y, v.z, v.w};
            #pragma unroll
            for (int j = 0; j < 4; j++) {
                uint32_t hi = f2tf32(xs[j]);
                qh[base + 2 * j] = hi;
                ql[base + 2 * j] = f2tf32(xs[j] - __uint_as_float(hi));
            }
        }
        #pragma unroll
        for (int i = 0; i < 2; i++) {
            int u = tid + i * 256;
            int n = u >> 3, kq = u & 7;
            float4 v = make_float4(0.f, 0.f, 0.f, 0.f);
            if (n < NN) v = *reinterpret_cast<const float4*>(k + (size_t)n * ldx + k0 + 4 * kq);
            int base = n * 36 + 4 * kq;
            float xs[4] = {v.x, v.y, v.z, v.w};
            #pragma unroll
            for (int j = 0; j < 4; j++) {
                uint32_t hi = f2tf32(xs[j]);
                kh[base + j] = hi;
                kl[base + j] = f2tf32(xs[j] - __uint_as_float(hi));
            }
        }
        __syncthreads();

        {
            const uint32_t* khp = &kh[rn * 36 + rq * 8];
            const uint32_t* klp = &kl[rn * 36 + rq * 8];
            const float* c1p = cv + k0 + rq * 8;
            const float* c2p = cv + NF + k0 + rq * 8;
            #pragma unroll
            for (int kk = 0; kk < 8; kk++) {
                float xm = __uint_as_float(khp[kk]) + __uint_as_float(klp[kk]);
                racc1 += xm * c1p[kk];
                racc2 += xm * c2p[kk];
            }
        }

        #pragma unroll
        for (int s = 0; s < 4; s++) {
            uint32_t ah[2][4], al[2][4], bh[2][2], bl[2][2];
            #pragma unroll
            for (int mt = 0; mt < 2; mt++) {
                int r0 = wm + mt * 16 + gid;
                uint2 t0 = *reinterpret_cast<const uint2*>(&qh[(r0    ) * 40 + 8 * s + 2 * cq]);
                uint2 t1 = *reinterpret_cast<const uint2*>(&qh[(r0 + 8) * 40 + 8 * s + 2 * cq]);
                ah[mt][0] = t0.x; ah[mt][1] = t1.x; ah[mt][2] = t0.y; ah[mt][3] = t1.y;
                uint2 u0 = *reinterpret_cast<const uint2*>(&ql[(r0    ) * 40 + 8 * s + 2 * cq]);
                uint2 u1 = *reinterpret_cast<const uint2*>(&ql[(r0 + 8) * 40 + 8 * s + 2 * cq]);
                al[mt][0] = u0.x; al[mt][1] = u1.x; al[mt][2] = u0.y; al[mt][3] = u1.y;
            }
            #pragma unroll
            for (int nt = 0; nt < 2; nt++) {
                int n = wn + 8 * nt + gid;
                bh[nt][0] = kh[n * 36 + 8 * s + cq];
                bh[nt][1] = kh[n * 36 + 8 * s + cq + 4];
                bl[nt][0] = kl[n * 36 + 8 * s + cq];
                bl[nt][1] = kl[n * 36 + 8 * s + cq + 4];
            }
            #pragma unroll
            for (int mt = 0; mt < 2; mt++)
                #pragma unroll
                for (int nt = 0; nt < 2; nt++) {
                    mma_tf32(acc[mt][nt], ah[mt], bh[nt]);
                    mma_tf32(acc[mt][nt], ah[mt], bl[nt]);
                    mma_tf32(acc[mt][nt], al[mt], bh[nt]);
                }
        }
    }

    #pragma unroll
    for (int o = 1; o <= 2; o <<= 1) {
        racc1 += __shfl_xor_sync(0xffffffffu, racc1, o);
        racc2 += __shfl_xor_sync(0xffffffffu, racc2, o);
    }
    if (rq == 0) { r1s[rn] = racc1; r2s[rn] = racc2; }
    __syncthreads();

    float* sq   = reinterpret_cast<float*>(sbuf);
    float* rinv = reinterpret_cast<float*>(sbuf) + 4400;

    #pragma unroll
    for (int mt = 0; mt < 2; mt++)
        #pragma unroll
        for (int nt = 0; nt < 2; nt++) {
            int r = wm + 16 * mt + gid;
            int c = wn + 8 * nt + 2 * cq;
            float d0 = acc[mt][nt][0] + r1s[r    ] + r2s[c    ] + c3;
            float d1 = acc[mt][nt][1] + r1s[r    ] + r2s[c + 1] + c3;
            float d2 = acc[mt][nt][2] + r1s[r + 8] + r2s[c    ] + c3;
            float d3 = acc[mt][nt][3] + r1s[r + 8] + r2s[c + 1] + c3;
            sq[(r    ) * 68 + c    ] = (c     < NN) ? d0 * d0 : 0.f;
            sq[(r    ) * 68 + c + 1] = (c + 1 < NN) ? d1 * d1 : 0.f;
            sq[(r + 8) * 68 + c    ] = (c     < NN) ? d2 * d2 : 0.f;
            sq[(r + 8) * 68 + c + 1] = (c + 1 < NN) ? d3 * d3 : 0.f;
        }
    __syncthreads();

    for (int r = wid; r < NN; r += 8) {
        float s = sq[r * 68 + lane] + sq[r * 68 + 32 + lane];
        #pragma unroll
        for (int o = 16; o; o >>= 1) s += __shfl_xor_sync(0xffffffffu, s, o);
        if (lane == 0) rinv[r] = 1.f / fmaxf(s, 1e-12f);
    }
    __syncthreads();

    for (int idx = tid; idx < NN * NN; idx += 256) {
        int n = idx / NN, m = idx - n * NN;
        ADJ[(size_t)b * NN * NN + idx] = sq[n * 68 + m] * rinv[n];
    }
}

// ---------------------------------------------------------------------------
// Fused GCN layer with packed f32x2 FMA over node-pairs (round-12 version).
// ---------------------------------------------------------------------------
template<int NN, bool MEAN>
__global__ __launch_bounds__(768, 1)
void gcn_fused(const float* __restrict__ ADJ, const float* __restrict__ XW, int ldxw,
               const float* __restrict__ g, const float* __restrict__ bb,
               float* __restrict__ OUT)
{
    constexpr int NP = NN / 2;
    extern __shared__ float sm[];
    float* adjs = sm;
    float* mu   = sm + NN * NN;
    float* rs   = mu + NN;
    float* h    = rs + NN;

    const int b = blockIdx.x;
    const int j = threadIdx.x;
    const int w = j >> 5, lane = j & 31;

    unsigned long long xc2[NP];
    #pragma unroll
    for (int mi = 0; mi < NP; mi++) {
        float x0 = XW[((size_t)b * NN + 2 * mi    ) * ldxw + j];
        float x1 = XW[((size_t)b * NN + 2 * mi + 1) * ldxw + j];
        xc2[mi] = pack_f32x2(x0, x1);
    }

    for (int idx = j; idx < NN * NN; idx += 768)
        adjs[idx] = ADJ[(size_t)b * NN * NN + idx];
    __syncthreads();

    for (int n = 0; n < NN; n++) {
        const unsigned long long* arow =
            reinterpret_cast<const unsigned long long*>(&adjs[n * NN]);
        unsigned long long a2 = 0ull;
        #pragma unroll
        for (int mi = 0; mi < NP; mi++)
            a2 = fma_f32x2(arow[mi], xc2[mi], a2);
        float lo, hi;
        unpack_f32x2(a2, lo, hi);
        h[n * NF + j] = lo + hi;
    }
    __syncthreads();

    for (int r = w; r < NN; r += 24) {
        float s = 0.f, ss = 0.f;
        #pragma unroll
        for (int c = lane; c < NF; c += 32) {
            float v = h[r * NF + c];
            s += v; ss += v * v;
        }
        #pragma unroll
        for (int o = 16; o; o >>= 1) {
            s  += __shfl_xor_sync(0xffffffffu, s, o);
            ss += __shfl_xor_sync(0xffffffffu, ss, o);
        }
        if (lane == 0) {
            float m_ = s * (1.f / NF);
            mu[r] = m_;
            rs[r] = rsqrtf(ss * (1.f / NF) - m_ * m_ + 1e-5f);
        }
    }
    __syncthreads();

    const float gg = g[j], bv = bb[j];
    if (MEAN) {
        float macc = 0.f;
        for (int n = 0; n < NN; n++) {
            float v = (h[n * NF + j] - mu[n]) * rs[n] * gg + bv;
            macc += fmaxf(v, 0.f);
        }
        OUT[(size_t)b * NF + j] = macc * (1.f / NN);
    } else {
        for (int n = 0; n < NN; n++) {
            float v = (h[n * NF + j] - mu[n]) * rs[n] * gg + bv;
            OUT[((size_t)b * NN + n) * NF + j] = fmaxf(v, 0.f);
        }
    }
}

// ---------------------------------------------------------------------------
// Skinny classifier GEMM (M=16), W original [N][K] row-major.
// ---------------------------------------------------------------------------
template<bool RELU>
__global__ __launch_bounds__(256, 1)
void skinny_fc(const float* __restrict__ A, const float* __restrict__ W,
               const float* __restrict__ bias, float* __restrict__ out,
               int N, int K, int ldo)
{
    extern __shared__ float ys[];
    const int tid = threadIdx.x, w = tid >> 5, lane = tid & 31;

    for (int idx = tid; idx < 16 * K; idx += 256) ys[idx] = A[idx];
    __syncthreads();

    int n = blockIdx.x * 8 + w;
    if (n >= N) return;

    float acc[16];
    #pragma unroll
    for (int m = 0; m < 16; m++) acc[m] = 0.f;

    const float* wp = W + (size_t)n * K;
    for (int k0 = 0; k0 < K; k0 += 32) {
        float wv = wp[k0 + lane];
        #pragma unroll
        for (int m = 0; m < 16; m++)
            acc[m] = fmaf(wv, ys[m * K + k0 + lane], acc[m]);
    }
    #pragma unroll
    for (int m = 0; m < 16; m++) {
        float s = acc[m];
        #pragma unroll
        for (int o = 16; o; o >>= 1) s += __shfl_xor_sync(0xffffffffu, s, o);
        if (lane == 0) {
            float v = s + bias[n];
            if (RELU) v = fmaxf(v, 0.f);
            out[(size_t)m * ldo + n] = v;
        }
    }
}

// ---------------------------------------------------------------------------
// Prep kernels
// ---------------------------------------------------------------------------
__global__ void transpose_kernel(const float* __restrict__ in, float* __restrict__ out,
                                 int R, int C, int ldo, int col_off)
{
    __shared__ float t[32][33];
    int bx = blockIdx.x * 32, by = blockIdx.y * 32;
    int x = bx + threadIdx.x;
    for (int i = threadIdx.y; i < 32; i += 8) {
        int y = by + i;
        t[i][threadIdx.x] = (y < R && x < C) ? in[(size_t)y * C + x] : 0.f;
    }
    __syncthreads();
    int ox = by + threadIdx.x;
    for (int i = threadIdx.y; i < 32; i += 8) {
        int oy = bx + i;
        if (oy < C && ox < R) out[(size_t)oy * ldo + col_off + ox] = t[threadIdx.x][i];
    }
}

// copy W0 into wcomb cols [768..1536), tf32-rounded + col-permuted
__global__ void copy_w0_kernel(const float* __restrict__ w0, float* __restrict__ wcomb)
{
    int k = blockIdx.x;
    for (int n = threadIdx.x; n < NF; n += 256)
        wcomb[(size_t)k * NZW + NF + COLPERM(n)] =
            __uint_as_float(f2tf32(w0[(size_t)k * NF + n]));
}

// raw-bit col-permuted copy of W1 (numerics identical: HMMA truncates)
__global__ void w1_perm_kernel(const float* __restrict__ in, float* __restrict__ out)
{
    int k = blockIdx.x;
    for (int n = threadIdx.x; n < NF; n += 256)
        out[(size_t)k * NF + COLPERM(n)] = in[(size_t)k * NF + n];
}

// partial dots, 32 row-chunks of 24 for latency hiding
__global__ void cvec_part(const float* __restrict__ wq, const float* __restrict__ wk,
                          const float* __restrict__ bq, const float* __restrict__ bk,
                          float* __restrict__ cpart)
{
    int d = blockIdx.x * 256 + threadIdx.x;
    int ic = blockIdx.y;                     // 0..31
    const float* W  = (d < NF) ? wq : wk;
    const float* bv = (d < NF) ? bk : bq;
    int dd = (d < NF) ? d : d - NF;
    float s = 0.f;
    int i0 = ic * 24;
    #pragma unroll 4
    for (int i = i0; i < i0 + 24; i++)
        s += W[(size_t)i * NF + dd] * bv[i];
    cpart[(size_t)ic * 2 * NF + d] = s;
}

// combine partials; block 6 computes c3 = bq·bk
__global__ void cvec_comb(const float* __restrict__ cpart,
                          const float* __restrict__ bq, const float* __restrict__ bk,
                          float* __restrict__ cv)
{
    if (blockIdx.x < 6) {
        int d = blockIdx.x * 256 + threadIdx.x;
        float s = 0.f;
        #pragma unroll
        for (int g = 0; g < 32; g++) s += cpart[(size_t)g * 2 * NF + d];
        cv[d] = s;
    } else {
        __shared__ float red[8];
        int tid = threadIdx.x;
        float s = 0.f;
        for (int i = tid; i < NF; i += 256) s += bq[i] * bk[i];
        #pragma unroll
        for (int o = 16; o; o >>= 1) s += __shfl_xor_sync(0xffffffffu, s, o);
        if ((tid & 31) == 0) red[tid >> 5] = s;
        __syncthreads();
        if (tid == 0) {
            float t = 0.f;
            #pragma unroll
            for (int i = 0; i < 8; i++) t += red[i];
            cv[2 * NF] = t;
        }
    }
}

__global__ void concat_kernel(const float* __restrict__ a, const float* __restrict__ g2,
                              float* __restrict__ y, int d)
{
    const int i = blockIdx.x;
    for (int jj = threadIdx.x; jj < d; jj += 256) {
        y[(size_t)i * 2 * d + jj]     = a[(size_t)i * d + jj];
        y[(size_t)i * 2 * d + d + jj] = g2[(size_t)i * d + jj];
    }
}

// ---------------------------------------------------------------------------
// Host side
// ---------------------------------------------------------------------------
static inline dim3 gemm_grid(int M, int N) {
    return dim3((N + 127) / 128, (M + 127) / 128);
}

template<int NN>
static void run_graph(const float* x_in, int Bt,
                      const float* wcomb, const float* w1, const float* cv,
                      const float* ln_g, const float* ln_b,
                      float* p_zxw, float* p_xw, float* p_x, float* p_adj,
                      float* out_mean, size_t sm_fused)
{
    const int M = Bt * NN;
    gemm_tf32<<<gemm_grid(M, NZW), 256, GEMM_SMEM>>>(
        x_in, wcomb, p_zxw, M, NZW, NF, NF, NZW, NZW);
    adj_mma<NN><<<Bt, 256>>>(p_zxw, NZW, x_in, NF, cv, p_adj);
    gcn_fused<NN, false><<<Bt, 768, sm_fused>>>(p_adj, p_zxw + NF, NZW, ln_g, ln_b, p_x);
    gemm_tf32<<<gemm_grid(M, NF), 256, GEMM_SMEM>>>(
        p_x, w1, p_xw, M, NF, NF, NF, NF, NF);
    gcn_fused<NN, true><<<Bt, 768, sm_fused>>>(p_adj, p_xw, NF, ln_g + NF, ln_b + NF, out_mean);
}

extern "C" void kernel_launch(void* const* d_in, const int* in_sizes, int n_in,
                              void* d_out, int out_size)
{
    const float* feats  = (const float*)d_in[0];
    const float* fglob  = (const float*)d_in[1];
    const float* wq_w   = (const float*)d_in[3];
    const float* wq_b   = (const float*)d_in[4];
    const float* wk_w   = (const float*)d_in[5];
    const float* wk_b   = (const float*)d_in[6];
    const float* gcn_w  = (const float*)d_in[7];
    const float* ln_g   = (const float*)d_in[8];
    const float* ln_b   = (const float*)d_in[9];
    const float* fc1_w  = (const float*)d_in[10];
    const float* fc1_b  = (const float*)d_in[11];
    const float* fc2_w  = (const float*)d_in[12];
    const float* fc2_b  = (const float*)d_in[13];
    float* out = (float*)d_out;

    float *p_zxw, *p_xw, *p_x, *p_adj, *p_mean, *p_mean2, *p_hc;
    float *p_wcomb, *p_w1p, *p_wqT, *p_cv, *p_cpart;
    cudaGetSymbolAddress((void**)&p_zxw,  g_zxw);
    cudaGetSymbolAddress((void**)&p_xw,   g_xw);
    cudaGetSymbolAddress((void**)&p_x,    g_x);
    cudaGetSymbolAddress((void**)&p_adj,  g_adj);
    cudaGetSymbolAddress((void**)&p_mean, g_mean);
    cudaGetSymbolAddress((void**)&p_mean2,g_mean2);
    cudaGetSymbolAddress((void**)&p_hc,   g_hc);
    cudaGetSymbolAddress((void**)&p_wcomb,g_wcomb);
    cudaGetSymbolAddress((void**)&p_w1p,  g_w1p);
    cudaGetSymbolAddress((void**)&p_wqT,  g_wqT);
    cudaGetSymbolAddress((void**)&p_cv,   g_cvec);
    cudaGetSymbolAddress((void**)&p_cpart,g_cpart);

    const size_t sm50 = (size_t)(NN1 * NN1 + 2 * NN1 + NN1 * NF) * 4;
    const size_t sm32 = (size_t)(NN2 * NN2 + 2 * NN2 + NN2 * NF) * 4;
    const size_t smfc1 = 16 * (size_t)NF2 * 4;
    const size_t smfc2 = 16 * (size_t)NF  * 4;
    cudaFuncSetAttribute(gcn_fused<NN1, false>, cudaFuncAttributeMaxDynamicSharedMemorySize, (int)sm50);
    cudaFuncSetAttribute(gcn_fused<NN1, true >, cudaFuncAttributeMaxDynamicSharedMemorySize, (int)sm50);
    cudaFuncSetAttribute(gcn_fused<NN2, false>, cudaFuncAttributeMaxDynamicSharedMemorySize, (int)sm32);
    cudaFuncSetAttribute(gcn_fused<NN2, true >, cudaFuncAttributeMaxDynamicSharedMemorySize, (int)sm32);
    cudaFuncSetAttribute(gemm_tf32,  cudaFuncAttributeMaxDynamicSharedMemorySize, GEMM_SMEM);
    cudaFuncSetAttribute(gemm_split, cudaFuncAttributeMaxDynamicSharedMemorySize, GEMM_SMEM);
    cudaFuncSetAttribute(skinny_fc<true >, cudaFuncAttributeMaxDynamicSharedMemorySize, (int)smfc1);
    cudaFuncSetAttribute(skinny_fc<false>, cudaFuncAttributeMaxDynamicSharedMemorySize, (int)smfc2);

    // ---- prep: wcomb = [A | W0] (tf32-rounded, col-permuted); W1 permuted ----
    dim3 tb(32, 8);
    transpose_kernel<<<dim3(NF / 32, NF / 32), tb>>>(wq_w, p_wqT, NF, NF, NF, 0);
    gemm_split<<<gemm_grid(NF, NF), 256, GEMM_SMEM>>>(
        p_wqT, wk_w, p_wcomb, NF, NF, NF, NF, NF, NZW);
    copy_w0_kernel<<<NF, 256>>>(gcn_w, p_wcomb);
    w1_perm_kernel<<<NF, 256>>>(gcn_w + (size_t)NF * NF, p_w1p);
    cvec_part<<<dim3(6, 32), 256>>>(wq_w, wk_w, wq_b, wk_b, p_cpart);
    cvec_comb<<<7, 256>>>(p_cpart, wq_b, wk_b, p_cv);

    // ---- graph pass 1: [512, 50, 768] -> [512, 768] ----
    run_graph<NN1>(feats, NB1, p_wcomb, p_w1p, p_cv, ln_g, ln_b,
                   p_zxw, p_xw, p_x, p_adj, p_mean, sm50);

    // ---- graph pass 2: [16, 32, 768] -> [16, 768] ----
    run_graph<NN2>(p_mean, NB2, p_wcomb, p_w1p, p_cv, ln_g, ln_b,
                   p_zxw, p_xw, p_x, p_adj, p_mean2, sm32);

    // ---- classifier ----
    float* y_out = out + NB2 * NC;
    concat_kernel<<<NB2, 256>>>(p_mean2, fglob, y_out, NF);
    skinny_fc<true ><<<NF / 8, 256, smfc1>>>(y_out, fc1_w, fc1_b, p_hc, NF, NF2, NF);
    skinny_fc<false><<<NC / 8, 256, smfc2>>>(p_hc, fc2_w, fc2_b, out, NC, NF, NC);
}

// round 15
// speedup vs baseline: 1.0924x; 1.0924x over previous
#include <cuda_runtime.h>
#include <cstdint>

// ---------------------------------------------------------------------------
// Problem constants
// ---------------------------------------------------------------------------
#define NF   768
#define NB1  512
#define NN1  50
#define NB2  16
#define NN2  32
#define M1   (NB1*NN1)    // 25600
#define NC   400
#define NF2  (2*NF)
#define NZW  1536         // combined z|xw width

// ---------------------------------------------------------------------------
// Scratch (device globals)
// ---------------------------------------------------------------------------
__device__ float g_zxw [(size_t)M1 * NZW];    // z | xw, ld=1536
__device__ float g_xw  [(size_t)M1 * NF];
__device__ float g_x   [(size_t)M1 * NF];
__device__ float g_adj [(size_t)NB1 * NN1 * NN1];
__device__ float g_mean[(size_t)NB1 * NF];
__device__ float g_mean2[(size_t)NB2 * NF];
__device__ float g_hc  [(size_t)NB2 * NF];
__device__ float g_wcomb[(size_t)NF * NZW];   // [K=768][N=1536]: A | W0 (tf32-rounded)
__device__ float g_wqT [(size_t)NF * NF];
__device__ float g_cvec[2 * NF + 1];          // c1 | c2 | c3
__device__ float g_cpart[32 * 2 * NF];

// ---------------------------------------------------------------------------
// helpers
// ---------------------------------------------------------------------------
__device__ __forceinline__ uint32_t smem_to_u32(const void* p) {
    uint32_t a;
    asm("{ .reg .u64 t; cvta.to.shared.u64 t, %1; cvt.u32.u64 %0, t; }"
        : "=r"(a) : "l"(p));
    return a;
}

__device__ __forceinline__ uint32_t f2tf32(float f) {
    uint32_t r;
    asm("cvt.rna.tf32.f32 %0, %1;" : "=r"(r) : "f"(f));
    return r;
}

__device__ __forceinline__ void mma_tf32(float* d, const uint32_t* a, const uint32_t* b) {
    asm volatile(
        "mma.sync.aligned.m16n8k8.row.col.f32.tf32.tf32.f32 "
        "{%0,%1,%2,%3}, {%4,%5,%6,%7}, {%8,%9}, {%0,%1,%2,%3};"
        : "+f"(d[0]), "+f"(d[1]), "+f"(d[2]), "+f"(d[3])
        : "r"(a[0]), "r"(a[1]), "r"(a[2]), "r"(a[3]), "r"(b[0]), "r"(b[1]));
}

__device__ __forceinline__ void cp_async16(uint32_t dst, const void* src) {
    asm volatile("cp.async.cg.shared.global [%0], [%1], 16;"
                 :: "r"(dst), "l"(src) : "memory");
}
#define CP_COMMIT() asm volatile("cp.async.commit_group;" ::: "memory")
#define CP_WAIT0()  asm volatile("cp.async.wait_group 0;" ::: "memory")

__device__ __forceinline__ unsigned long long fma_f32x2(
    unsigned long long a, unsigned long long b, unsigned long long c) {
    unsigned long long d;
    asm("fma.rn.f32x2 %0, %1, %2, %3;" : "=l"(d) : "l"(a), "l"(b), "l"(c));
    return d;
}
__device__ __forceinline__ unsigned long long pack_f32x2(float lo, float hi) {
    unsigned long long p;
    asm("mov.b64 %0, {%1, %2};" : "=l"(p) : "f"(lo), "f"(hi));
    return p;
}
__device__ __forceinline__ void unpack_f32x2(unsigned long long p, float& lo, float& hi) {
    asm("mov.b64 {%0, %1}, %2;" : "=f"(lo), "=f"(hi) : "l"(p));
}

// ---------------------------------------------------------------------------
// Pipelined TF32 GEMM: C = A[M,K] @ B[K,N]; HMMA truncates both operands.
// 128x128x32 tile, 256 threads.
// A: float4 reg-prefetch, raw-bit STS with row-local j-XOR swizzle
//    (conflict-free stores AND fragment loads).
// B: cp.async double-buffered; BNP=136 -> conflict-free 32-bit B-frag LDS.
// Epilogue: STG.64 paired stores.
// M%128==0, N%128==0, K%32==0.
// ---------------------------------------------------------------------------
#define GEMM_SMEM 75776

__global__ __launch_bounds__(256, 2)
void gemm_tf32(const float* __restrict__ A, const float* __restrict__ B,
               float* __restrict__ C, int M, int N, int K,
               int lda, int ldb, int ldc)
{
    constexpr int BK = 32, AKP = 40, BNP = 136;
    constexpr int ASZ = 128 * AKP, BSZ = BK * BNP;
    extern __shared__ uint32_t smg[];
    uint32_t* Ab = smg;             // [2][ASZ]
    uint32_t* Bb = smg + 2 * ASZ;   // [2][BSZ]
    const uint32_t sbB = smem_to_u32(Bb);

    const int tid  = threadIdx.x;
    const int wid  = tid >> 5, lane = tid & 31;
    const int gid  = lane >> 2, cq = lane & 3;
    const int wm   = (wid >> 2) * 64, wn = (wid & 3) * 32;
    const int row0 = blockIdx.y * 128, col0 = blockIdx.x * 128;
    const int NK   = K / BK;
    const int cqx  = 2 * (cq ^ (gid & 3));

    int bk[4], bn4[4];
    #pragma unroll
    for (int i = 0; i < 4; i++) {
        int u = tid + i * 256;
        bk[i]  = u >> 5;
        bn4[i] = (u & 31) * 4;
    }

    #pragma unroll
    for (int i = 0; i < 4; i++)
        cp_async16(sbB + (uint32_t)(bk[i] * BNP + bn4[i]) * 4,
                   B + (size_t)bk[i] * ldb + col0 + bn4[i]);
    CP_COMMIT();

    float4 rA[4];
    #pragma unroll
    for (int i = 0; i < 4; i++) {
        int u = tid + i * 256, m = u >> 3, kq = u & 7;
        rA[i] = *reinterpret_cast<const float4*>(A + (size_t)(row0 + m) * lda + 4 * kq);
    }

    float acc[4][4][4];
    #pragma unroll
    for (int i = 0; i < 4; i++)
        #pragma unroll
        for (int j = 0; j < 4; j++)
            #pragma unroll
            for (int q = 0; q < 4; q++) acc[i][j][q] = 0.f;

    for (int s = 0; s < NK; s++) {
        const int p = s & 1;
        uint32_t* Ap = Ab + p * ASZ;
        uint32_t* Bp = Bb + p * BSZ;

        #pragma unroll
        for (int i = 0; i < 4; i++) {
            int u = tid + i * 256, m = u >> 3, kq = u & 7;
            int r = m & 3;
            int base = m * AKP + 8 * (kq >> 1) + (kq & 1);
            Ap[base + 2 * (0 ^ r)] = __float_as_uint(rA[i].x);
            Ap[base + 2 * (1 ^ r)] = __float_as_uint(rA[i].y);
            Ap[base + 2 * (2 ^ r)] = __float_as_uint(rA[i].z);
            Ap[base + 2 * (3 ^ r)] = __float_as_uint(rA[i].w);
        }
        CP_WAIT0();
        __syncthreads();
        if (s + 1 < NK) {
            const float* Bn = B + (size_t)(s + 1) * BK * ldb + col0;
            #pragma unroll
            for (int i = 0; i < 4; i++)
                cp_async16(sbB + (uint32_t)((p ^ 1) * BSZ + bk[i] * BNP + bn4[i]) * 4,
                           Bn + (size_t)bk[i] * ldb + bn4[i]);
            CP_COMMIT();
            #pragma unroll
            for (int i = 0; i < 4; i++) {
                int u = tid + i * 256, m = u >> 3, kq = u & 7;
                rA[i] = *reinterpret_cast<const float4*>(
                    A + (size_t)(row0 + m) * lda + (s + 1) * BK + 4 * kq);
            }
        }

        #pragma unroll
        for (int st = 0; st < 4; st++) {
            uint32_t af[4][4];
            #pragma unroll
            for (int mt = 0; mt < 4; mt++) {
                int r0 = wm + mt * 16 + gid;
                uint2 t0 = *reinterpret_cast<const uint2*>(&Ap[(r0    ) * AKP + 8 * st + cqx]);
                uint2 t1 = *reinterpret_cast<const uint2*>(&Ap[(r0 + 8) * AKP + 8 * st + cqx]);
                af[mt][0] = t0.x; af[mt][1] = t1.x; af[mt][2] = t0.y; af[mt][3] = t1.y;
            }
            uint32_t bf[4][2];
            #pragma unroll
            for (int nt = 0; nt < 4; nt++) {
                int cn = wn + nt * 8 + gid;
                bf[nt][0] = Bp[(8 * st + cq    ) * BNP + cn];
                bf[nt][1] = Bp[(8 * st + cq + 4) * BNP + cn];
            }
            #pragma unroll
            for (int mt = 0; mt < 4; mt++)
                #pragma unroll
                for (int nt = 0; nt < 4; nt++)
                    mma_tf32(acc[mt][nt], af[mt], bf[nt]);
        }
    }

    // epilogue: paired STG.64 (cc, cc+1 contiguous)
    #pragma unroll
    for (int mt = 0; mt < 4; mt++) {
        int rlo = row0 + wm + mt * 16 + gid;
        int rhi = rlo + 8;
        #pragma unroll
        for (int nt = 0; nt < 4; nt++) {
            int cc = col0 + wn + nt * 8 + 2 * cq;
            *reinterpret_cast<float2*>(&C[(size_t)rlo * ldc + cc]) =
                make_float2(acc[mt][nt][0], acc[mt][nt][1]);
            *reinterpret_cast<float2*>(&C[(size_t)rhi * ldc + cc]) =
                make_float2(acc[mt][nt][2], acc[mt][nt][3]);
        }
    }
}

// ---------------------------------------------------------------------------
// Split-tf32 GEMM (fp32-accurate) — prep only (A = wq^T @ wk).
// ---------------------------------------------------------------------------
__global__ __launch_bounds__(256, 1)
void gemm_split(const float* __restrict__ A, const float* __restrict__ B,
                float* __restrict__ C, int M, int N, int K,
                int lda, int ldb, int ldc)
{
    constexpr int BK = 32, AKP = 40, BNP = 136;
    constexpr int ASZ = 128 * AKP, BSZ = BK * BNP;
    extern __shared__ uint32_t smg[];
    uint32_t* Ah = smg;
    uint32_t* Al = smg + ASZ;
    uint32_t* Bh = smg + 2 * ASZ;
    uint32_t* Bl = smg + 2 * ASZ + BSZ;

    const int tid  = threadIdx.x;
    const int wid  = tid >> 5, lane = tid & 31;
    const int gid  = lane >> 2, cq = lane & 3;
    const int wm   = (wid >> 2) * 64, wn = (wid & 3) * 32;
    const int row0 = blockIdx.y * 128, col0 = blockIdx.x * 128;

    float acc[4][4][4];
    #pragma unroll
    for (int i = 0; i < 4; i++)
        #pragma unroll
        for (int j = 0; j < 4; j++)
            #pragma unroll
            for (int q = 0; q < 4; q++) acc[i][j][q] = 0.f;

    for (int k0 = 0; k0 < K; k0 += BK) {
        __syncthreads();
        #pragma unroll
        for (int i = 0; i < 4; i++) {
            int u = tid + i * 256, m = u >> 3, kq = u & 7;
            int gm = row0 + m;
            float4 v = (gm < M) ? *reinterpret_cast<const float4*>(A + (size_t)gm * lda + k0 + 4 * kq)
                                : make_float4(0.f, 0.f, 0.f, 0.f);
            int base = m * AKP + 8 * (kq >> 1) + (kq & 1);
            float xs[4] = {v.x, v.y, v.z, v.w};
            #pragma unroll
            for (int j = 0; j < 4; j++) {
                uint32_t hi = f2tf32(xs[j]);
                Ah[base + 2 * j] = hi;
                Al[base + 2 * j] = f2tf32(xs[j] - __uint_as_float(hi));
            }
        }
        #pragma unroll
        for (int i = 0; i < 4; i++) {
            int u = tid + i * 256, k = u >> 5, nq = u & 31;
            int gn = col0 + 4 * nq;
            const float* bp = B + (size_t)(k0 + k) * ldb + gn;
            int base = k * BNP + 4 * nq;
            #pragma unroll
            for (int j = 0; j < 4; j++) {
                float x = (gn + j < N) ? bp[j] : 0.f;
                uint32_t hi = f2tf32(x);
                Bh[base + j] = hi;
                Bl[base + j] = f2tf32(x - __uint_as_float(hi));
            }
        }
        __syncthreads();

        #pragma unroll
        for (int s = 0; s < 4; s++) {
            uint32_t ah[4][4], al[4][4];
            #pragma unroll
            for (int mt = 0; mt < 4; mt++) {
                int r0 = wm + mt * 16 + gid;
                uint2 t0 = *reinterpret_cast<const uint2*>(&Ah[(r0    ) * AKP + 8 * s + 2 * cq]);
                uint2 t1 = *reinterpret_cast<const uint2*>(&Ah[(r0 + 8) * AKP + 8 * s + 2 * cq]);
                ah[mt][0] = t0.x; ah[mt][1] = t1.x; ah[mt][2] = t0.y; ah[mt][3] = t1.y;
                uint2 u0 = *reinterpret_cast<const uint2*>(&Al[(r0    ) * AKP + 8 * s + 2 * cq]);
                uint2 u1 = *reinterpret_cast<const uint2*>(&Al[(r0 + 8) * AKP + 8 * s + 2 * cq]);
                al[mt][0] = u0.x; al[mt][1] = u1.x; al[mt][2] = u0.y; al[mt][3] = u1.y;
            }
            uint32_t bh[4][2], bl[4][2];
            #pragma unroll
            for (int nt = 0; nt < 4; nt++) {
                int cn = wn + nt * 8 + gid;
                bh[nt][0] = Bh[(8 * s + cq    ) * BNP + cn];
                bh[nt][1] = Bh[(8 * s + cq + 4) * BNP + cn];
                bl[nt][0] = Bl[(8 * s + cq    ) * BNP + cn];
                bl[nt][1] = Bl[(8 * s + cq + 4) * BNP + cn];
            }
            #pragma unroll
            for (int mt = 0; mt < 4; mt++)
                #pragma unroll
                for (int nt = 0; nt < 4; nt++) {
                    mma_tf32(acc[mt][nt], ah[mt], bh[nt]);
                    mma_tf32(acc[mt][nt], ah[mt], bl[nt]);
                    mma_tf32(acc[mt][nt], al[mt], bh[nt]);
                }
        }
    }

    #pragma unroll
    for (int mt = 0; mt < 4; mt++) {
        int rlo = row0 + wm + mt * 16 + gid;
        int rhi = rlo + 8;
        #pragma unroll
        for (int nt = 0; nt < 4; nt++) {
            int cc = col0 + wn + nt * 8 + 2 * cq;
            if (rlo < M) {
                if (cc     < N) C[(size_t)rlo * ldc + cc    ] = __uint_as_float(f2tf32(acc[mt][nt][0]));
                if (cc + 1 < N) C[(size_t)rlo * ldc + cc + 1] = __uint_as_float(f2tf32(acc[mt][nt][1]));
            }
            if (rhi < M) {
                if (cc     < N) C[(size_t)rhi * ldc + cc    ] = __uint_as_float(f2tf32(acc[mt][nt][2]));
                if (cc + 1 < N) C[(size_t)rhi * ldc + cc + 1] = __uint_as_float(f2tf32(acc[mt][nt][3]));
            }
        }
    }
}

// ---------------------------------------------------------------------------
// adj_mma: per batch b, split-tf32 dot = z @ x^T; r1/r2 computed in-kernel.
// adj = dot^2 / max(rowsum(dot^2), 1e-12)
// ---------------------------------------------------------------------------
template<int NN>
__global__ __launch_bounds__(256, 2)
void adj_mma(const float* __restrict__ Z, int ldz,
             const float* __restrict__ X, int ldx,
             const float* __restrict__ cv, float* __restrict__ ADJ)
{
    __shared__ __align__(16) uint32_t sbuf[9728];
    __shared__ float r1s[64], r2s[64];
    uint32_t* qh = sbuf;
    uint32_t* ql = sbuf + 2560;
    uint32_t* kh = sbuf + 5120;
    uint32_t* kl = sbuf + 7424;

    const int b = blockIdx.x, tid = threadIdx.x;
    const int wid = tid >> 5, lane = tid & 31;
    const int gid = lane >> 2, cq = lane & 3;
    const int wm = (wid >> 2) * 32, wn = (wid & 3) * 16;

    const float c3 = cv[2 * NF];
    const int rn = tid >> 2;
    const int rq = tid & 3;

    const float* q = Z + (size_t)b * NN * ldz;
    const float* k = X + (size_t)b * NN * ldx;

    float acc[2][2][4];
    #pragma unroll
    for (int a = 0; a < 2; a++)
        #pragma unroll
        for (int c = 0; c < 2; c++)
            #pragma unroll
            for (int e = 0; e < 4; e++) acc[a][c][e] = 0.f;

    float racc1 = 0.f, racc2 = 0.f;

    for (int k0 = 0; k0 < NF; k0 += 32) {
        __syncthreads();
        #pragma unroll
        for (int i = 0; i < 2; i++) {
            int u = tid + i * 256;
            int m = u >> 3, kq = u & 7;
            float4 v = make_float4(0.f, 0.f, 0.f, 0.f);
            if (m < NN) v = *reinterpret_cast<const float4*>(q + (size_t)m * ldz + k0 + 4 * kq);
            int base = m * 40 + 8 * (kq >> 1) + (kq & 1);
            float xs[4] = {v.x, v.y, v.z, v.w};
            #pragma unroll
            for (int j = 0; j < 4; j++) {
                uint32_t hi = f2tf32(xs[j]);
                qh[base + 2 * j] = hi;
                ql[base + 2 * j] = f2tf32(xs[j] - __uint_as_float(hi));
            }
        }
        #pragma unroll
        for (int i = 0; i < 2; i++) {
            int u = tid + i * 256;
            int n = u >> 3, kq = u & 7;
            float4 v = make_float4(0.f, 0.f, 0.f, 0.f);
            if (n < NN) v = *reinterpret_cast<const float4*>(k + (size_t)n * ldx + k0 + 4 * kq);
            int base = n * 36 + 4 * kq;
            float xs[4] = {v.x, v.y, v.z, v.w};
            #pragma unroll
            for (int j = 0; j < 4; j++) {
                uint32_t hi = f2tf32(xs[j]);
                kh[base + j] = hi;
                kl[base + j] = f2tf32(xs[j] - __uint_as_float(hi));
            }
        }
        __syncthreads();

        {
            const uint32_t* khp = &kh[rn * 36 + rq * 8];
            const uint32_t* klp = &kl[rn * 36 + rq * 8];
            const float* c1p = cv + k0 + rq * 8;
            const float* c2p = cv + NF + k0 + rq * 8;
            #pragma unroll
            for (int kk = 0; kk < 8; kk++) {
                float xm = __uint_as_float(khp[kk]) + __uint_as_float(klp[kk]);
                racc1 += xm * c1p[kk];
                racc2 += xm * c2p[kk];
            }
        }

        #pragma unroll
        for (int s = 0; s < 4; s++) {
            uint32_t ah[2][4], al[2][4], bh[2][2], bl[2][2];
            #pragma unroll
            for (int mt = 0; mt < 2; mt++) {
                int r0 = wm + mt * 16 + gid;
                uint2 t0 = *reinterpret_cast<const uint2*>(&qh[(r0    ) * 40 + 8 * s + 2 * cq]);
                uint2 t1 = *reinterpret_cast<const uint2*>(&qh[(r0 + 8) * 40 + 8 * s + 2 * cq]);
                ah[mt][0] = t0.x; ah[mt][1] = t1.x; ah[mt][2] = t0.y; ah[mt][3] = t1.y;
                uint2 u0 = *reinterpret_cast<const uint2*>(&ql[(r0    ) * 40 + 8 * s + 2 * cq]);
                uint2 u1 = *reinterpret_cast<const uint2*>(&ql[(r0 + 8) * 40 + 8 * s + 2 * cq]);
                al[mt][0] = u0.x; al[mt][1] = u1.x; al[mt][2] = u0.y; al[mt][3] = u1.y;
            }
            #pragma unroll
            for (int nt = 0; nt < 2; nt++) {
                int n = wn + 8 * nt + gid;
                bh[nt][0] = kh[n * 36 + 8 * s + cq];
                bh[nt][1] = kh[n * 36 + 8 * s + cq + 4];
                bl[nt][0] = kl[n * 36 + 8 * s + cq];
                bl[nt][1] = kl[n * 36 + 8 * s + cq + 4];
            }
            #pragma unroll
            for (int mt = 0; mt < 2; mt++)
                #pragma unroll
                for (int nt = 0; nt < 2; nt++) {
                    mma_tf32(acc[mt][nt], ah[mt], bh[nt]);
                    mma_tf32(acc[mt][nt], ah[mt], bl[nt]);
                    mma_tf32(acc[mt][nt], al[mt], bh[nt]);
                }
        }
    }

    #pragma unroll
    for (int o = 1; o <= 2; o <<= 1) {
        racc1 += __shfl_xor_sync(0xffffffffu, racc1, o);
        racc2 += __shfl_xor_sync(0xffffffffu, racc2, o);
    }
    if (rq == 0) { r1s[rn] = racc1; r2s[rn] = racc2; }
    __syncthreads();

    float* sq   = reinterpret_cast<float*>(sbuf);
    float* rinv = reinterpret_cast<float*>(sbuf) + 4400;

    #pragma unroll
    for (int mt = 0; mt < 2; mt++)
        #pragma unroll
        for (int nt = 0; nt < 2; nt++) {
            int r = wm + 16 * mt + gid;
            int c = wn + 8 * nt + 2 * cq;
            float d0 = acc[mt][nt][0] + r1s[r    ] + r2s[c    ] + c3;
            float d1 = acc[mt][nt][1] + r1s[r    ] + r2s[c + 1] + c3;
            float d2 = acc[mt][nt][2] + r1s[r + 8] + r2s[c    ] + c3;
            float d3 = acc[mt][nt][3] + r1s[r + 8] + r2s[c + 1] + c3;
            sq[(r    ) * 68 + c    ] = (c     < NN) ? d0 * d0 : 0.f;
            sq[(r    ) * 68 + c + 1] = (c + 1 < NN) ? d1 * d1 : 0.f;
            sq[(r + 8) * 68 + c    ] = (c     < NN) ? d2 * d2 : 0.f;
            sq[(r + 8) * 68 + c + 1] = (c + 1 < NN) ? d3 * d3 : 0.f;
        }
    __syncthreads();

    for (int r = wid; r < NN; r += 8) {
        float s = sq[r * 68 + lane] + sq[r * 68 + 32 + lane];
        #pragma unroll
        for (int o = 16; o; o >>= 1) s += __shfl_xor_sync(0xffffffffu, s, o);
        if (lane == 0) rinv[r] = 1.f / fmaxf(s, 1e-12f);
    }
    __syncthreads();

    for (int idx = tid; idx < NN * NN; idx += 256) {
        int n = idx / NN, m = idx - n * NN;
        ADJ[(size_t)b * NN * NN + idx] = sq[n * 68 + m] * rinv[n];
    }
}

// ---------------------------------------------------------------------------
// Fused GCN layer with packed f32x2 FMA over node-pairs (round-12 version).
// ---------------------------------------------------------------------------
template<int NN, bool MEAN>
__global__ __launch_bounds__(768, 1)
void gcn_fused(const float* __restrict__ ADJ, const float* __restrict__ XW, int ldxw,
               const float* __restrict__ g, const float* __restrict__ bb,
               float* __restrict__ OUT)
{
    constexpr int NP = NN / 2;
    extern __shared__ float sm[];
    float* adjs = sm;
    float* mu   = sm + NN * NN;
    float* rs   = mu + NN;
    float* h    = rs + NN;

    const int b = blockIdx.x;
    const int j = threadIdx.x;
    const int w = j >> 5, lane = j & 31;

    unsigned long long xc2[NP];
    #pragma unroll
    for (int mi = 0; mi < NP; mi++) {
        float x0 = XW[((size_t)b * NN + 2 * mi    ) * ldxw + j];
        float x1 = XW[((size_t)b * NN + 2 * mi + 1) * ldxw + j];
        xc2[mi] = pack_f32x2(x0, x1);
    }

    for (int idx = j; idx < NN * NN; idx += 768)
        adjs[idx] = ADJ[(size_t)b * NN * NN + idx];
    __syncthreads();

    for (int n = 0; n < NN; n++) {
        const unsigned long long* arow =
            reinterpret_cast<const unsigned long long*>(&adjs[n * NN]);
        unsigned long long a2 = 0ull;
        #pragma unroll
        for (int mi = 0; mi < NP; mi++)
            a2 = fma_f32x2(arow[mi], xc2[mi], a2);
        float lo, hi;
        unpack_f32x2(a2, lo, hi);
        h[n * NF + j] = lo + hi;
    }
    __syncthreads();

    for (int r = w; r < NN; r += 24) {
        float s = 0.f, ss = 0.f;
        #pragma unroll
        for (int c = lane; c < NF; c += 32) {
            float v = h[r * NF + c];
            s += v; ss += v * v;
        }
        #pragma unroll
        for (int o = 16; o; o >>= 1) {
            s  += __shfl_xor_sync(0xffffffffu, s, o);
            ss += __shfl_xor_sync(0xffffffffu, ss, o);
        }
        if (lane == 0) {
            float m_ = s * (1.f / NF);
            mu[r] = m_;
            rs[r] = rsqrtf(ss * (1.f / NF) - m_ * m_ + 1e-5f);
        }
    }
    __syncthreads();

    const float gg = g[j], bv = bb[j];
    if (MEAN) {
        float macc = 0.f;
        for (int n = 0; n < NN; n++) {
            float v = (h[n * NF + j] - mu[n]) * rs[n] * gg + bv;
            macc += fmaxf(v, 0.f);
        }
        OUT[(size_t)b * NF + j] = macc * (1.f / NN);
    } else {
        for (int n = 0; n < NN; n++) {
            float v = (h[n * NF + j] - mu[n]) * rs[n] * gg + bv;
            OUT[((size_t)b * NN + n) * NF + j] = fmaxf(v, 0.f);
        }
    }
}

// ---------------------------------------------------------------------------
// Skinny classifier GEMM (M=16), W original [N][K] row-major.
// ---------------------------------------------------------------------------
template<bool RELU>
__global__ __launch_bounds__(256, 1)
void skinny_fc(const float* __restrict__ A, const float* __restrict__ W,
               const float* __restrict__ bias, float* __restrict__ out,
               int N, int K, int ldo)
{
    extern __shared__ float ys[];
    const int tid = threadIdx.x, w = tid >> 5, lane = tid & 31;

    for (int idx = tid; idx < 16 * K; idx += 256) ys[idx] = A[idx];
    __syncthreads();

    int n = blockIdx.x * 8 + w;
    if (n >= N) return;

    float acc[16];
    #pragma unroll
    for (int m = 0; m < 16; m++) acc[m] = 0.f;

    const float* wp = W + (size_t)n * K;
    for (int k0 = 0; k0 < K; k0 += 32) {
        float wv = wp[k0 + lane];
        #pragma unroll
        for (int m = 0; m < 16; m++)
            acc[m] = fmaf(wv, ys[m * K + k0 + lane], acc[m]);
    }
    #pragma unroll
    for (int m = 0; m < 16; m++) {
        float s = acc[m];
        #pragma unroll
        for (int o = 16; o; o >>= 1) s += __shfl_xor_sync(0xffffffffu, s, o);
        if (lane == 0) {
            float v = s + bias[n];
            if (RELU) v = fmaxf(v, 0.f);
            out[(size_t)m * ldo + n] = v;
        }
    }
}

// ---------------------------------------------------------------------------
// Prep kernels
// ---------------------------------------------------------------------------
__global__ void transpose_kernel(const float* __restrict__ in, float* __restrict__ out,
                                 int R, int C, int ldo, int col_off)
{
    __shared__ float t[32][33];
    int bx = blockIdx.x * 32, by = blockIdx.y * 32;
    int x = bx + threadIdx.x;
    for (int i = threadIdx.y; i < 32; i += 8) {
        int y = by + i;
        t[i][threadIdx.x] = (y < R && x < C) ? in[(size_t)y * C + x] : 0.f;
    }
    __syncthreads();
    int ox = by + threadIdx.x;
    for (int i = threadIdx.y; i < 32; i += 8) {
        int oy = bx + i;
        if (oy < C && ox < R) out[(size_t)oy * ldo + col_off + ox] = t[threadIdx.x][i];
    }
}

// copy W0 into wcomb cols [768..1536), tf32-rounded
__global__ void copy_w0_kernel(const float* __restrict__ w0, float* __restrict__ wcomb)
{
    int k = blockIdx.x;
    for (int n = threadIdx.x; n < NF; n += 256)
        wcomb[(size_t)k * NZW + NF + n] = __uint_as_float(f2tf32(w0[(size_t)k * NF + n]));
}

// partial dots, 32 row-chunks of 24 for latency hiding
__global__ void cvec_part(const float* __restrict__ wq, const float* __restrict__ wk,
                          const float* __restrict__ bq, const float* __restrict__ bk,
                          float* __restrict__ cpart)
{
    int d = blockIdx.x * 256 + threadIdx.x;
    int ic = blockIdx.y;                     // 0..31
    const float* W  = (d < NF) ? wq : wk;
    const float* bv = (d < NF) ? bk : bq;
    int dd = (d < NF) ? d : d - NF;
    float s = 0.f;
    int i0 = ic * 24;
    #pragma unroll 4
    for (int i = i0; i < i0 + 24; i++)
        s += W[(size_t)i * NF + dd] * bv[i];
    cpart[(size_t)ic * 2 * NF + d] = s;
}

// combine partials; block 6 computes c3 = bq·bk
__global__ void cvec_comb(const float* __restrict__ cpart,
                          const float* __restrict__ bq, const float* __restrict__ bk,
                          float* __restrict__ cv)
{
    if (blockIdx.x < 6) {
        int d = blockIdx.x * 256 + threadIdx.x;
        float s = 0.f;
        #pragma unroll
        for (int g = 0; g < 32; g++) s += cpart[(size_t)g * 2 * NF + d];
        cv[d] = s;
    } else {
        __shared__ float red[8];
        int tid = threadIdx.x;
        float s = 0.f;
        for (int i = tid; i < NF; i += 256) s += bq[i] * bk[i];
        #pragma unroll
        for (int o = 16; o; o >>= 1) s += __shfl_xor_sync(0xffffffffu, s, o);
        if ((tid & 31) == 0) red[tid >> 5] = s;
        __syncthreads();
        if (tid == 0) {
            float t = 0.f;
            #pragma unroll
            for (int i = 0; i < 8; i++) t += red[i];
            cv[2 * NF] = t;
        }
    }
}

__global__ void concat_kernel(const float* __restrict__ a, const float* __restrict__ g2,
                              float* __restrict__ y, int d)
{
    const int i = blockIdx.x;
    for (int jj = threadIdx.x; jj < d; jj += 256) {
        y[(size_t)i * 2 * d + jj]     = a[(size_t)i * d + jj];
        y[(size_t)i * 2 * d + d + jj] = g2[(size_t)i * d + jj];
    }
}

// ---------------------------------------------------------------------------
// Host side
// ---------------------------------------------------------------------------
static inline dim3 gemm_grid(int M, int N) {
    return dim3((N + 127) / 128, (M + 127) / 128);
}

template<int NN>
static void run_graph(const float* x_in, int Bt,
                      const float* wcomb, const float* w1, const float* cv,
                      const float* ln_g, const float* ln_b,
                      float* p_zxw, float* p_xw, float* p_x, float* p_adj,
                      float* out_mean, size_t sm_fused)
{
    const int M = Bt * NN;
    gemm_tf32<<<gemm_grid(M, NZW), 256, GEMM_SMEM>>>(
        x_in, wcomb, p_zxw, M, NZW, NF, NF, NZW, NZW);
    adj_mma<NN><<<Bt, 256>>>(p_zxw, NZW, x_in, NF, cv, p_adj);
    gcn_fused<NN, false><<<Bt, 768, sm_fused>>>(p_adj, p_zxw + NF, NZW, ln_g, ln_b, p_x);
    gemm_tf32<<<gemm_grid(M, NF), 256, GEMM_SMEM>>>(
        p_x, w1, p_xw, M, NF, NF, NF, NF, NF);
    gcn_fused<NN, true><<<Bt, 768, sm_fused>>>(p_adj, p_xw, NF, ln_g + NF, ln_b + NF, out_mean);
}

extern "C" void kernel_launch(void* const* d_in, const int* in_sizes, int n_in,
                              void* d_out, int out_size)
{
    const float* feats  = (const float*)d_in[0];
    const float* fglob  = (const float*)d_in[1];
    const float* wq_w   = (const float*)d_in[3];
    const float* wq_b   = (const float*)d_in[4];
    const float* wk_w   = (const float*)d_in[5];
    const float* wk_b   = (const float*)d_in[6];
    const float* gcn_w  = (const float*)d_in[7];
    const float* ln_g   = (const float*)d_in[8];
    const float* ln_b   = (const float*)d_in[9];
    const float* fc1_w  = (const float*)d_in[10];
    const float* fc1_b  = (const float*)d_in[11];
    const float* fc2_w  = (const float*)d_in[12];
    const float* fc2_b  = (const float*)d_in[13];
    float* out = (float*)d_out;

    float *p_zxw, *p_xw, *p_x, *p_adj, *p_mean, *p_mean2, *p_hc;
    float *p_wcomb, *p_wqT, *p_cv, *p_cpart;
    cudaGetSymbolAddress((void**)&p_zxw,  g_zxw);
    cudaGetSymbolAddress((void**)&p_xw,   g_xw);
    cudaGetSymbolAddress((void**)&p_x,    g_x);
    cudaGetSymbolAddress((void**)&p_adj,  g_adj);
    cudaGetSymbolAddress((void**)&p_mean, g_mean);
    cudaGetSymbolAddress((void**)&p_mean2,g_mean2);
    cudaGetSymbolAddress((void**)&p_hc,   g_hc);
    cudaGetSymbolAddress((void**)&p_wcomb,g_wcomb);
    cudaGetSymbolAddress((void**)&p_wqT,  g_wqT);
    cudaGetSymbolAddress((void**)&p_cv,   g_cvec);
    cudaGetSymbolAddress((void**)&p_cpart,g_cpart);

    const size_t sm50 = (size_t)(NN1 * NN1 + 2 * NN1 + NN1 * NF) * 4;
    const size_t sm32 = (size_t)(NN2 * NN2 + 2 * NN2 + NN2 * NF) * 4;
    const size_t smfc1 = 16 * (size_t)NF2 * 4;
    const size_t smfc2 = 16 * (size_t)NF  * 4;
    cudaFuncSetAttribute(gcn_fused<NN1, false>, cudaFuncAttributeMaxDynamicSharedMemorySize, (int)sm50);
    cudaFuncSetAttribute(gcn_fused<NN1, true >, cudaFuncAttributeMaxDynamicSharedMemorySize, (int)sm50);
    cudaFuncSetAttribute(gcn_fused<NN2, false>, cudaFuncAttributeMaxDynamicSharedMemorySize, (int)sm32);
    cudaFuncSetAttribute(gcn_fused<NN2, true >, cudaFuncAttributeMaxDynamicSharedMemorySize, (int)sm32);
    cudaFuncSetAttribute(gemm_tf32,  cudaFuncAttributeMaxDynamicSharedMemorySize, GEMM_SMEM);
    cudaFuncSetAttribute(gemm_split, cudaFuncAttributeMaxDynamicSharedMemorySize, GEMM_SMEM);
    cudaFuncSetAttribute(skinny_fc<true >, cudaFuncAttributeMaxDynamicSharedMemorySize, (int)smfc1);
    cudaFuncSetAttribute(skinny_fc<false>, cudaFuncAttributeMaxDynamicSharedMemorySize, (int)smfc2);

    // ---- prep: wcomb = [A | W0] as [768][1536] (tf32-rounded) ----
    dim3 tb(32, 8);
    transpose_kernel<<<dim3(NF / 32, NF / 32), tb>>>(wq_w, p_wqT, NF, NF, NF, 0);
    gemm_split<<<gemm_grid(NF, NF), 256, GEMM_SMEM>>>(
        p_wqT, wk_w, p_wcomb, NF, NF, NF, NF, NF, NZW);
    copy_w0_kernel<<<NF, 256>>>(gcn_w, p_wcomb);
    cvec_part<<<dim3(6, 32), 256>>>(wq_w, wk_w, wq_b, wk_b, p_cpart);
    cvec_comb<<<7, 256>>>(p_cpart, wq_b, wk_b, p_cv);

    // W1 used directly from input (HMMA truncates operands to tf32 in-flight)
    const float* w1 = gcn_w + (size_t)NF * NF;

    // ---- graph pass 1: [512, 50, 768] -> [512, 768] ----
    run_graph<NN1>(feats, NB1, p_wcomb, w1, p_cv, ln_g, ln_b,
                   p_zxw, p_xw, p_x, p_adj, p_mean, sm50);

    // ---- graph pass 2: [16, 32, 768] -> [16, 768] ----
    run_graph<NN2>(p_mean, NB2, p_wcomb, w1, p_cv, ln_g, ln_b,
                   p_zxw, p_xw, p_x, p_adj, p_mean2, sm32);

    // ---- classifier ----
    float* y_out = out + NB2 * NC;
    concat_kernel<<<NB2, 256>>>(p_mean2, fglob, y_out, NF);
    skinny_fc<true ><<<NF / 8, 256, smfc1>>>(y_out, fc1_w, fc1_b, p_hc, NF, NF2, NF);
    skinny_fc<false><<<NC / 8, 256, smfc2>>>(p_hc, fc2_w, fc2_b, out, NC, NF, NC);
}